// round 4
// baseline (speedup 1.0000x reference)
#include <cuda_runtime.h>
#include <cstdint>

// Problem constants
#define NB   16
#define NL   128
#define NE   300
#define NH   512
#define NT   9
#define NBIOE 64
#define NREL 128
#define NR   50

// ---------------- scratch layout (floats) ----------------
#define EMB_OFF    0            // 2048*300
#define EMBR_OFF   614400       // 2048*300
#define BSUM_OFF   1228800      // 2*2048
#define XP_OFF     1232896      // 2 * 2048*2048
#define HS_OFF     9621504      // 2 * 128*16*512
#define CBUF_OFF   11718656     // 2 * 16*512
#define OBUF_OFF   11735040     // 2048*512
#define EMI_OFF    12783616     // 2048*9
#define OC_OFF     12802048     // 2048*576
#define U_OFF      13981696     // 2048*128
#define V_OFF      14243840     // 2048*128
#define U1_OFF     14505984     // 2048*128
#define V2_OFF     14768128     // 2048*128
#define MASKF_OFF  15030272     // 2048
#define SCRATCH_SZ 15032320

__device__ __align__(16) float g_scratch[SCRATCH_SZ];
__device__ double g_sel_sum;
__device__ int    g_mask_count;
__device__ float  g_crf_loss;

__device__ __forceinline__ float sigm(float x) { return 1.f / (1.f + expf(-x)); }

// ---------------- zero accumulators ----------------
__global__ void zero_kernel() {
    g_sel_sum = 0.0;
    g_mask_count = 0;
    g_crf_loss = 0.f;
}

// ---------------- embedding gather + mask ----------------
__global__ void embed_kernel(const int* __restrict__ tokens,
                             const float* __restrict__ wemb) {
    int idx = blockIdx.x * blockDim.x + threadIdx.x;   // < 2048*300
    int bl = idx / NE;
    int e  = idx - bl * NE;
    int tok = tokens[bl];
    g_scratch[EMB_OFF + idx] = wemb[(size_t)tok * NE + e];
    if (e == 0) {
        g_scratch[MASKF_OFF + bl] = (tok != 0) ? 1.f : 0.f;
        if (tok != 0) atomicAdd(&g_mask_count, 1);
    }
}

__global__ void embrev_kernel() {
    int idx = blockIdx.x * blockDim.x + threadIdx.x;   // < 2048*300
    int b = idx / (NL * NE);
    int rem = idx - b * (NL * NE);
    int l = rem / NE;
    int e = rem - l * NE;
    g_scratch[EMBR_OFF + idx] = g_scratch[EMB_OFF + (size_t)(b * NL + (NL - 1 - l)) * NE + e];
}

// ---------------- combined biases ----------------
__global__ void bsum_kernel(const float* bif, const float* bhf,
                            const float* bib, const float* bhb) {
    int idx = blockIdx.x * blockDim.x + threadIdx.x;   // < 4096
    int d = idx >> 11, g = idx & 2047;
    g_scratch[BSUM_OFF + idx] = d ? (bib[g] + bhb[g]) : (bif[g] + bhf[g]);
}

// ---------------- generic NT SGEMM: C[M,N] = A[M,K] * B[N,K]^T (+bias, relu) ----
__global__ __launch_bounds__(256) void sgemm_nt(
    int aOff, int lda, const float* __restrict__ Bm, int ldb,
    int cOff, int N, int K,
    const float* __restrict__ biasExt, int biasOff, int relu)
{
    __shared__ float As[64][33];
    __shared__ float Bs[64][33];
    int tid = threadIdx.x;
    int tx = tid & 15, ty = tid >> 4;
    int rowBase = blockIdx.y * 64;
    int colBase = blockIdx.x * 64;
    const float* A = g_scratch + aOff;

    float acc[4][4];
#pragma unroll
    for (int i = 0; i < 4; i++)
#pragma unroll
        for (int j = 0; j < 4; j++) acc[i][j] = 0.f;

    for (int k0 = 0; k0 < K; k0 += 32) {
#pragma unroll
        for (int i = 0; i < 8; i++) {
            int p = tid + i * 256;
            int r = p >> 5, c = p & 31;
            int gk = k0 + c;
            As[r][c] = (gk < K) ? A[(size_t)(rowBase + r) * lda + gk] : 0.f;
            Bs[r][c] = (gk < K) ? Bm[(size_t)(colBase + r) * ldb + gk] : 0.f;
        }
        __syncthreads();
#pragma unroll
        for (int k = 0; k < 32; k++) {
            float a0 = As[ty * 4 + 0][k], a1 = As[ty * 4 + 1][k];
            float a2 = As[ty * 4 + 2][k], a3 = As[ty * 4 + 3][k];
            float b0 = Bs[tx * 4 + 0][k], b1 = Bs[tx * 4 + 1][k];
            float b2 = Bs[tx * 4 + 2][k], b3 = Bs[tx * 4 + 3][k];
            acc[0][0] += a0 * b0; acc[0][1] += a0 * b1; acc[0][2] += a0 * b2; acc[0][3] += a0 * b3;
            acc[1][0] += a1 * b0; acc[1][1] += a1 * b1; acc[1][2] += a1 * b2; acc[1][3] += a1 * b3;
            acc[2][0] += a2 * b0; acc[2][1] += a2 * b1; acc[2][2] += a2 * b2; acc[2][3] += a2 * b3;
            acc[3][0] += a3 * b0; acc[3][1] += a3 * b1; acc[3][2] += a3 * b2; acc[3][3] += a3 * b3;
        }
        __syncthreads();
    }

    float* C = g_scratch + cOff;
#pragma unroll
    for (int i = 0; i < 4; i++) {
        int row = rowBase + ty * 4 + i;
#pragma unroll
        for (int jn = 0; jn < 4; jn++) {
            int col = colBase + tx * 4 + jn;
            float v = acc[i][jn];
            if (biasExt) v += biasExt[col];
            else if (biasOff >= 0) v += g_scratch[biasOff + col];
            if (relu) v = fmaxf(v, 0.f);
            C[(size_t)row * N + col] = v;
        }
    }
}

// ---------------- one LSTM timestep, both directions fused --------------------
// grid 128 blocks: dir(2) x j-tile(16 of 32) x n-tile(4 of 4 batches); 128 thr.
__global__ __launch_bounds__(128) void lstm_step_kernel(
    const float* __restrict__ whhf, const float* __restrict__ whhb, int t)
{
    int bx = blockIdx.x;
    int dir = bx & 1;
    int jt  = (bx >> 1) & 15;
    int nt  = (bx >> 5) & 3;
    const float* whh = dir ? whhb : whhf;

    __shared__ __align__(16) float sh[2048];   // h_prev for 4 batches
    __shared__ float pre[512];                 // gate preacts (4 gates x 4 n x 32 j)

    int tid = threadIdx.x;
    for (int p = tid; p < 2048; p += 128) {
        float v = 0.f;
        if (t > 0) {
            int nn = p >> 9, k = p & 511;
            v = g_scratch[HS_OFF + (size_t)dir * 1048576 + (size_t)(t - 1) * 8192
                          + (size_t)(nt * 4 + nn) * 512 + k];
        }
        sh[p] = v;
    }
    __syncthreads();

    int gk = tid >> 5, jj = tid & 31;
    int j  = jt * 32 + jj;
    int gr = gk * 512 + j;                     // gate row in [0,2048)
    const float4* w4 = reinterpret_cast<const float4*>(whh) + (size_t)gr * 128;
    const float4* h4 = reinterpret_cast<const float4*>(sh);
    float a0 = 0.f, a1 = 0.f, a2 = 0.f, a3 = 0.f;
#pragma unroll 4
    for (int kk = 0; kk < 128; kk++) {
        float4 w  = w4[kk];
        float4 h0 = h4[0 * 128 + kk];
        float4 h1 = h4[1 * 128 + kk];
        float4 h2 = h4[2 * 128 + kk];
        float4 h3 = h4[3 * 128 + kk];
        a0 += w.x * h0.x + w.y * h0.y + w.z * h0.z + w.w * h0.w;
        a1 += w.x * h1.x + w.y * h1.y + w.z * h1.z + w.w * h1.w;
        a2 += w.x * h2.x + w.y * h2.y + w.z * h2.z + w.w * h2.w;
        a3 += w.x * h3.x + w.y * h3.y + w.z * h3.z + w.w * h3.w;
    }
    const float* xp = g_scratch + XP_OFF + (size_t)dir * 4194304;
    pre[(gk * 4 + 0) * 32 + jj] = a0 + xp[(size_t)((nt * 4 + 0) * NL + t) * 2048 + gr];
    pre[(gk * 4 + 1) * 32 + jj] = a1 + xp[(size_t)((nt * 4 + 1) * NL + t) * 2048 + gr];
    pre[(gk * 4 + 2) * 32 + jj] = a2 + xp[(size_t)((nt * 4 + 2) * NL + t) * 2048 + gr];
    pre[(gk * 4 + 3) * 32 + jj] = a3 + xp[(size_t)((nt * 4 + 3) * NL + t) * 2048 + gr];
    __syncthreads();

    // cell update: 128 threads = 4 n x 32 j
    int nn = tid >> 5;
    int jj2 = tid & 31;
    float iv = pre[(0 * 4 + nn) * 32 + jj2];
    float fv = pre[(1 * 4 + nn) * 32 + jj2];
    float gv = pre[(2 * 4 + nn) * 32 + jj2];
    float ov = pre[(3 * 4 + nn) * 32 + jj2];
    int n  = nt * 4 + nn;
    int jd = jt * 32 + jj2;
    float* cbuf = g_scratch + CBUF_OFF + (size_t)dir * 8192;
    float cold = (t == 0) ? 0.f : cbuf[n * 512 + jd];
    float cnew = sigm(fv) * cold + sigm(iv) * tanhf(gv);
    float hnew = sigm(ov) * tanhf(cnew);
    cbuf[n * 512 + jd] = cnew;
    g_scratch[HS_OFF + (size_t)dir * 1048576 + (size_t)t * 8192 + (size_t)n * 512 + jd] = hnew;
}

// ---------------- o = 0.5*(hf + hb_rev) ----------------
__global__ void o_kernel() {
    int idx = blockIdx.x * blockDim.x + threadIdx.x;   // < 1048576
    int row = idx >> 9, j = idx & 511;
    int b = row >> 7, l = row & 127;
    float hf = g_scratch[HS_OFF + (size_t)l * 8192 + (size_t)b * 512 + j];
    float hb = g_scratch[HS_OFF + 1048576 + (size_t)(NL - 1 - l) * 8192 + (size_t)b * 512 + j];
    g_scratch[OBUF_OFF + idx] = 0.5f * (hf + hb);
}

// ---------------- emission: emi = o @ Ew^T + eb ----------------
__global__ void emi_kernel(const float* __restrict__ ew, const float* __restrict__ eb) {
    int idx = blockIdx.x * blockDim.x + threadIdx.x;
    if (idx >= 2048 * NT) return;
    int row = idx / NT, tag = idx - row * NT;
    const float4* o4 = reinterpret_cast<const float4*>(g_scratch + OBUF_OFF + (size_t)row * 512);
    const float4* w4 = reinterpret_cast<const float4*>(ew + (size_t)tag * 512);
    float s = 0.f;
#pragma unroll 4
    for (int k = 0; k < 128; k++) {
        float4 a = o4[k], b = w4[k];
        s += a.x * b.x + a.y * b.y + a.z * b.z + a.w * b.w;
    }
    g_scratch[EMI_OFF + idx] = s + eb[tag];
}

// ---------------- CRF NLL (tiny; 1 block) ----------------
__global__ void crf_kernel(const int* __restrict__ tokens, const int* __restrict__ tags,
                           const float* __restrict__ trans, const float* __restrict__ startv,
                           const float* __restrict__ endv)
{
    __shared__ float st[81], ss[9], se[9];
    __shared__ float alpha[16][9], nxt[16][9];
    __shared__ float num[16];
    __shared__ int prev[16];
    __shared__ float res[16];
    int tid = threadIdx.x;
    if (tid < 81) st[tid] = trans[tid];
    if (tid < 9) { ss[tid] = startv[tid]; se[tid] = endv[tid]; }
    __syncthreads();
    int b = tid / 9, j = tid - b * 9;
    const float* emi = g_scratch + EMI_OFF;
    if (tid < 144) {
        alpha[b][j] = ss[j] + emi[(size_t)(b * NL) * NT + j];
        if (j == 0) {
            int t0 = tags[b * NL];
            num[b] = ss[t0] + emi[(size_t)(b * NL) * NT + t0];
            prev[b] = t0;
        }
    }
    __syncthreads();
    for (int t = 1; t < NL; t++) {
        int m = 0;
        if (tid < 144) {
            m = (tokens[b * NL + t] != 0);
            float mx = -1e30f;
#pragma unroll
            for (int i = 0; i < 9; i++) mx = fmaxf(mx, alpha[b][i] + st[i * 9 + j]);
            float s = 0.f;
#pragma unroll
            for (int i = 0; i < 9; i++) s += expf(alpha[b][i] + st[i * 9 + j] - mx);
            float nv = mx + logf(s) + emi[(size_t)(b * NL + t) * NT + j];
            nxt[b][j] = m ? nv : alpha[b][j];
        }
        __syncthreads();
        if (tid < 144) {
            alpha[b][j] = nxt[b][j];
            if (j == 0 && m) {
                int tg = tags[b * NL + t];
                num[b] += st[prev[b] * 9 + tg] + emi[(size_t)(b * NL + t) * NT + tg];
                prev[b] = tg;
            }
        }
        __syncthreads();
    }
    if (tid < 16) {
        float nb = num[tid] + se[prev[tid]];
        float mx = -1e30f;
        for (int i2 = 0; i2 < 9; i2++) mx = fmaxf(mx, alpha[tid][i2] + se[i2]);
        float s = 0.f;
        for (int i2 = 0; i2 < 9; i2++) s += expf(alpha[tid][i2] + se[i2] - mx);
        res[tid] = nb - (mx + logf(s));
    }
    __syncthreads();
    if (tid == 0) {
        float tot = 0.f;
        for (int i2 = 0; i2 < 16; i2++) tot += res[i2];
        g_crf_loss = -tot / 16.f;
    }
}

// ---------------- oc = concat(o, bio_emb[bio_gold]) ----------------
__global__ void oc_kernel(const int* __restrict__ biog, const float* __restrict__ bemb) {
    int idx = blockIdx.x * blockDim.x + threadIdx.x;   // < 2048*576
    int row = idx / 576, k = idx - row * 576;
    float v = (k < 512) ? g_scratch[OBUF_OFF + (size_t)row * 512 + k]
                        : bemb[(size_t)biog[row] * NBIOE + (k - 512)];
    g_scratch[OC_OFF + idx] = v;
}

// ---------------- fused selection: uv build + einsum + BCE + masked sum -------
// grid 1024 blocks: (b, i-pair where i indexes V). 128 threads = j (indexes U).
__global__ __launch_bounds__(128) void sel_kernel(const int* __restrict__ gold,
                                                  const float* __restrict__ rel,
                                                  const float* __restrict__ uvb)
{
    __shared__ __align__(16) float srel[NR * NREL];   // 25.6KB
    __shared__ __align__(16) float sv0[NREL], sv1[NREL];
    __shared__ float sred[4];

    int bx = blockIdx.x;
    int b  = bx >> 6;
    int i0 = (bx & 63) << 1;
    int tid = threadIdx.x;

    for (int p = tid; p < NR * NREL; p += 128) srel[p] = rel[p];
    const float* v2 = g_scratch + V2_OFF;
    sv0[tid] = v2[(size_t)(b * NL + i0) * NREL + tid] + uvb[tid];
    sv1[tid] = v2[(size_t)(b * NL + i0 + 1) * NREL + tid] + uvb[tid];
    __syncthreads();

    int j = tid;
    const float4* u1r = reinterpret_cast<const float4*>(g_scratch + U1_OFF + (size_t)(b * NL + j) * NREL);
    const float4* s0_4 = reinterpret_cast<const float4*>(sv0);
    const float4* s1_4 = reinterpret_cast<const float4*>(sv1);
    const float4* rel4 = reinterpret_cast<const float4*>(srel);

    float acc0[NR], acc1[NR];
#pragma unroll
    for (int r = 0; r < NR; r++) { acc0[r] = 0.f; acc1[r] = 0.f; }

#pragma unroll 4
    for (int h4 = 0; h4 < 32; h4++) {
        float4 uu = u1r[h4];
        float4 a = s0_4[h4];
        float4 c = s1_4[h4];
        float x0x = fmaxf(uu.x + a.x, 0.f), x0y = fmaxf(uu.y + a.y, 0.f);
        float x0z = fmaxf(uu.z + a.z, 0.f), x0w = fmaxf(uu.w + a.w, 0.f);
        float x1x = fmaxf(uu.x + c.x, 0.f), x1y = fmaxf(uu.y + c.y, 0.f);
        float x1z = fmaxf(uu.z + c.z, 0.f), x1w = fmaxf(uu.w + c.w, 0.f);
#pragma unroll
        for (int r = 0; r < NR; r++) {
            float4 rv = rel4[r * 32 + h4];
            acc0[r] += x0x * rv.x + x0y * rv.y + x0z * rv.z + x0w * rv.w;
            acc1[r] += x1x * rv.x + x1y * rv.y + x1z * rv.z + x1w * rv.w;
        }
    }

    float mi0 = g_scratch[MASKF_OFF + b * NL + i0];
    float mi1 = g_scratch[MASKF_OFF + b * NL + i0 + 1];
    float mj  = g_scratch[MASKF_OFF + b * NL + j];
    const int* g0 = gold + (size_t)(b * NL + i0) * NR * NL + j;
    const int* g1 = gold + (size_t)(b * NL + i0 + 1) * NR * NL + j;
    float s0 = 0.f, s1 = 0.f;
#pragma unroll
    for (int r = 0; r < NR; r++) {
        float x = acc0[r];
        float gg = (float)g0[(size_t)r * NL];
        s0 += fmaxf(x, 0.f) - x * gg + log1pf(expf(-fabsf(x)));
        x = acc1[r];
        gg = (float)g1[(size_t)r * NL];
        s1 += fmaxf(x, 0.f) - x * gg + log1pf(expf(-fabsf(x)));
    }
    float part = mj * (mi0 * s0 + mi1 * s1);

#pragma unroll
    for (int off = 16; off; off >>= 1) part += __shfl_down_sync(0xFFFFFFFFu, part, off);
    if ((tid & 31) == 0) sred[tid >> 5] = part;
    __syncthreads();
    if (tid == 0) {
        double tot = (double)sred[0] + (double)sred[1] + (double)sred[2] + (double)sred[3];
        atomicAdd(&g_sel_sum, tot);
    }
}

// ---------------- final scalar ----------------
__global__ void final_kernel(float* out) {
    out[0] = g_crf_loss + (float)(g_sel_sum / (double)g_mask_count);
}

// ============================================================================
extern "C" void kernel_launch(void* const* d_in, const int* in_sizes, int n_in,
                              void* d_out, int out_size)
{
    const int*   tokens     = (const int*)d_in[0];
    const int*   bio_gold   = (const int*)d_in[1];
    const int*   sel_gold   = (const int*)d_in[2];
    // d_in[3] = is_train (unused)
    const float* word_emb   = (const float*)d_in[4];
    const float* rel_emb    = (const float*)d_in[5];
    const float* bio_emb    = (const float*)d_in[6];
    const float* w_ih_f     = (const float*)d_in[7];
    const float* w_hh_f     = (const float*)d_in[8];
    const float* b_ih_f     = (const float*)d_in[9];
    const float* b_hh_f     = (const float*)d_in[10];
    const float* w_ih_b     = (const float*)d_in[11];
    const float* w_hh_b     = (const float*)d_in[12];
    const float* b_ih_b     = (const float*)d_in[13];
    const float* b_hh_b     = (const float*)d_in[14];
    const float* emission_w = (const float*)d_in[15];
    const float* emission_b = (const float*)d_in[16];
    const float* sel_u_w    = (const float*)d_in[17];
    const float* sel_u_b    = (const float*)d_in[18];
    const float* sel_v_w    = (const float*)d_in[19];
    const float* sel_v_b    = (const float*)d_in[20];
    const float* sel_uv_w   = (const float*)d_in[21];
    const float* sel_uv_b   = (const float*)d_in[22];
    const float* crf_trans  = (const float*)d_in[23];
    const float* crf_start  = (const float*)d_in[24];
    const float* crf_end    = (const float*)d_in[25];

    zero_kernel<<<1, 1>>>();
    embed_kernel<<<2400, 256>>>(tokens, word_emb);
    embrev_kernel<<<2400, 256>>>();
    bsum_kernel<<<16, 256>>>(b_ih_f, b_hh_f, b_ih_b, b_hh_b);

    // xproj: (emb/emb_rev) @ w_ih^T + (b_ih + b_hh)
    sgemm_nt<<<dim3(32, 32), 256>>>(EMB_OFF, NE, w_ih_f, NE,
                                    XP_OFF, 2048, NE, nullptr, BSUM_OFF, 0);
    sgemm_nt<<<dim3(32, 32), 256>>>(EMBR_OFF, NE, w_ih_b, NE,
                                    XP_OFF + 4194304, 2048, NE, nullptr, BSUM_OFF + 2048, 0);

    for (int t = 0; t < NL; t++)
        lstm_step_kernel<<<128, 128>>>(w_hh_f, w_hh_b, t);

    o_kernel<<<4096, 256>>>();
    emi_kernel<<<(2048 * NT + 127) / 128, 128>>>(emission_w, emission_b);
    crf_kernel<<<1, 160>>>(tokens, bio_gold, crf_trans, crf_start, crf_end);

    oc_kernel<<<4608, 256>>>(bio_gold, bio_emb);
    // u = relu(oc @ sel_u_w^T + b), v likewise
    sgemm_nt<<<dim3(2, 32), 256>>>(OC_OFF, 576, sel_u_w, 576,
                                   U_OFF, NREL, 576, sel_u_b, -1, 1);
    sgemm_nt<<<dim3(2, 32), 256>>>(OC_OFF, 576, sel_v_w, 576,
                                   V_OFF, NREL, 576, sel_v_b, -1, 1);
    // u1 = u @ w1^T, v2 = v @ w2^T  (w1/w2 = halves of sel_uv_w, ldb=256)
    sgemm_nt<<<dim3(2, 32), 256>>>(U_OFF, NREL, sel_uv_w, 2 * NREL,
                                   U1_OFF, NREL, NREL, nullptr, -1, 0);
    sgemm_nt<<<dim3(2, 32), 256>>>(V_OFF, NREL, sel_uv_w + NREL, 2 * NREL,
                                   V2_OFF, NREL, NREL, nullptr, -1, 0);

    sel_kernel<<<1024, 128>>>(sel_gold, rel_emb, sel_uv_b);
    final_kernel<<<1, 1>>>((float*)d_out);
}

// round 6
// speedup vs baseline: 2.4692x; 2.4692x over previous
#include <cuda_runtime.h>
#include <cstdint>

// Problem constants
#define NB   16
#define NL   128
#define NE   300
#define NH   512
#define NT   9
#define NBIOE 64
#define NREL 128
#define NR   50

// ---------------- scratch layout (floats) ----------------
#define EMB_OFF    0            // 2048*300
#define EMBR_OFF   614400       // 2048*300
#define BSUM_OFF   1228800      // 2*2048
#define XP_OFF     1232896      // 2 * 2048*2048
#define HS_OFF     9621504      // 2 * 128*16*512
#define OBUF_OFF   11735040     // 2048*512
#define EMI_OFF    12783616     // 2048*9
#define OC_OFF     12802048     // 2048*576
#define U_OFF      13981696     // 2048*128
#define V_OFF      14243840     // 2048*128
#define U1_OFF     14505984     // 2048*128
#define V2_OFF     14768128     // 2048*128
#define MASKF_OFF  15030272     // 2048
#define SCRATCH_SZ 15032320

__device__ __align__(16) float g_scratch[SCRATCH_SZ];
__device__ double g_sel_sum;
__device__ int    g_mask_count;
__device__ float  g_crf_loss;
__device__ unsigned g_arrive;
__device__ unsigned g_release;

__device__ __forceinline__ float sigm(float x) { return 1.f / (1.f + expf(-x)); }

#define FMA_F32X2(d, a, b) \
    asm("fma.rn.f32x2 %0, %1, %2, %0;" : "+l"(d) : "l"(a), "l"(b))

// ---------------- zero accumulators ----------------
__global__ void zero_kernel() {
    g_sel_sum = 0.0;
    g_mask_count = 0;
    g_crf_loss = 0.f;
    g_arrive = 0u;
    g_release = 0u;
}

// ---------------- embedding gather + mask ----------------
__global__ void embed_kernel(const int* __restrict__ tokens,
                             const float* __restrict__ wemb) {
    int idx = blockIdx.x * blockDim.x + threadIdx.x;   // < 2048*300
    int bl = idx / NE;
    int e  = idx - bl * NE;
    int tok = tokens[bl];
    g_scratch[EMB_OFF + idx] = wemb[(size_t)tok * NE + e];
    if (e == 0) {
        g_scratch[MASKF_OFF + bl] = (tok != 0) ? 1.f : 0.f;
        if (tok != 0) atomicAdd(&g_mask_count, 1);
    }
}

__global__ void embrev_kernel() {
    int idx = blockIdx.x * blockDim.x + threadIdx.x;   // < 2048*300
    int b = idx / (NL * NE);
    int rem = idx - b * (NL * NE);
    int l = rem / NE;
    int e = rem - l * NE;
    g_scratch[EMBR_OFF + idx] = g_scratch[EMB_OFF + (size_t)(b * NL + (NL - 1 - l)) * NE + e];
}

// ---------------- combined biases ----------------
__global__ void bsum_kernel(const float* bif, const float* bhf,
                            const float* bib, const float* bhb) {
    int idx = blockIdx.x * blockDim.x + threadIdx.x;   // < 4096
    int d = idx >> 11, g = idx & 2047;
    g_scratch[BSUM_OFF + idx] = d ? (bib[g] + bhb[g]) : (bif[g] + bhf[g]);
}

// ---------------- generic NT SGEMM: C[M,N] = A[M,K] * B[N,K]^T (+bias, relu) ----
__global__ __launch_bounds__(256) void sgemm_nt(
    int aOff, int lda, const float* __restrict__ Bm, int ldb,
    int cOff, int N, int K,
    const float* __restrict__ biasExt, int biasOff, int relu)
{
    __shared__ float As[64][33];
    __shared__ float Bs[64][33];
    int tid = threadIdx.x;
    int tx = tid & 15, ty = tid >> 4;
    int rowBase = blockIdx.y * 64;
    int colBase = blockIdx.x * 64;
    const float* A = g_scratch + aOff;

    float acc[4][4];
#pragma unroll
    for (int i = 0; i < 4; i++)
#pragma unroll
        for (int j = 0; j < 4; j++) acc[i][j] = 0.f;

    for (int k0 = 0; k0 < K; k0 += 32) {
#pragma unroll
        for (int i = 0; i < 8; i++) {
            int p = tid + i * 256;
            int r = p >> 5, c = p & 31;
            int gk = k0 + c;
            As[r][c] = (gk < K) ? A[(size_t)(rowBase + r) * lda + gk] : 0.f;
            Bs[r][c] = (gk < K) ? Bm[(size_t)(colBase + r) * ldb + gk] : 0.f;
        }
        __syncthreads();
#pragma unroll
        for (int k = 0; k < 32; k++) {
            float a0 = As[ty * 4 + 0][k], a1 = As[ty * 4 + 1][k];
            float a2 = As[ty * 4 + 2][k], a3 = As[ty * 4 + 3][k];
            float b0 = Bs[tx * 4 + 0][k], b1 = Bs[tx * 4 + 1][k];
            float b2 = Bs[tx * 4 + 2][k], b3 = Bs[tx * 4 + 3][k];
            acc[0][0] += a0 * b0; acc[0][1] += a0 * b1; acc[0][2] += a0 * b2; acc[0][3] += a0 * b3;
            acc[1][0] += a1 * b0; acc[1][1] += a1 * b1; acc[1][2] += a1 * b2; acc[1][3] += a1 * b3;
            acc[2][0] += a2 * b0; acc[2][1] += a2 * b1; acc[2][2] += a2 * b2; acc[2][3] += a2 * b3;
            acc[3][0] += a3 * b0; acc[3][1] += a3 * b1; acc[3][2] += a3 * b2; acc[3][3] += a3 * b3;
        }
        __syncthreads();
    }

    float* C = g_scratch + cOff;
#pragma unroll
    for (int i = 0; i < 4; i++) {
        int row = rowBase + ty * 4 + i;
#pragma unroll
        for (int jn = 0; jn < 4; jn++) {
            int col = colBase + tx * 4 + jn;
            float v = acc[i][jn];
            if (biasExt) v += biasExt[col];
            else if (biasOff >= 0) v += g_scratch[biasOff + col];
            if (relu) v = fmaxf(v, 0.f);
            C[(size_t)row * N + col] = v;
        }
    }
}

// ---------------- persistent BiLSTM: all 128 timesteps in one kernel ---------
// Grid: 128 blocks = dir(2) x slice(64). Block owns 8 j's x 4 gates = 32 gate
// rows; W_hh slice lives in registers for the whole kernel. Per step:
// load h_prev[16][512] to smem; matvec in 2 passes of 8 batches (partials
// buffer = 8KB); gate fuse; write h to HS history; software grid barrier.
// smem: 32KB (h) + 8KB (partials) dynamic + 512B static = 40.5KB <= 48KB.
__global__ __launch_bounds__(256, 1) void lstm_persist(
    const float* __restrict__ whhf, const float* __restrict__ whhb)
{
    int bx  = blockIdx.x;
    int dir = bx & 1;
    int s   = bx >> 1;          // 0..63
    int j0  = s * 8;
    const float* whh = dir ? whhb : whhf;

    extern __shared__ float dsh[];
    float4* h4    = (float4*)dsh;          // 2048 float4 = 32KB: h_prev[16][512]
    float*  spart = dsh + 8192;            // [8][256] = 8KB partials
    __shared__ float sc[128];              // cell state for (b, jj)

    int tid = threadIdx.x;
    int row = tid & 31;                    // row within block's 32 gate rows
    int ks  = tid >> 5;                    // k-split 0..7 (64 k each)
    int g   = row >> 3, jj = row & 7;
    int gr  = g * 512 + j0 + jj;           // global gate row [0,2048)

    // preload W slice into registers as f32x2 pairs: W[gr][ks*64 .. ks*64+63]
    unsigned long long wreg[32];
    {
        const ulonglong2* wsrc =
            reinterpret_cast<const ulonglong2*>(whh + (size_t)gr * 512 + ks * 64);
#pragma unroll
        for (int kk = 0; kk < 16; kk++) {
            ulonglong2 w = wsrc[kk];
            wreg[2 * kk] = w.x;
            wreg[2 * kk + 1] = w.y;
        }
    }
    if (tid < 128) sc[tid] = 0.f;

    for (int t = 0; t < NL; t++) {
        // ---- load h_prev into smem ----
        if (t == 0) {
            float4 z = make_float4(0.f, 0.f, 0.f, 0.f);
            for (int p = tid; p < 2048; p += 256) h4[p] = z;
        } else {
            const float4* hsrc = reinterpret_cast<const float4*>(
                g_scratch + HS_OFF + (size_t)dir * 1048576 + (size_t)(t - 1) * 8192);
            for (int p = tid; p < 2048; p += 256) h4[p] = hsrc[p];
        }
        __syncthreads();

        // ---- matvec + fuse in two passes of 8 batches ----
#pragma unroll 1
        for (int g2 = 0; g2 < 2; g2++) {
#pragma unroll 1
            for (int b = 0; b < 8; b++) {
                int bb = g2 * 8 + b;
                const ulonglong2* hb =
                    reinterpret_cast<const ulonglong2*>(h4 + bb * 128 + ks * 16);
                unsigned long long acc2 = 0ull;    // (+0.f, +0.f)
#pragma unroll
                for (int kk = 0; kk < 16; kk++) {
                    ulonglong2 h2 = hb[kk];
                    FMA_F32X2(acc2, wreg[2 * kk], h2.x);
                    FMA_F32X2(acc2, wreg[2 * kk + 1], h2.y);
                }
                float2 af = *reinterpret_cast<float2*>(&acc2);
                spart[b * 256 + tid] = af.x + af.y;
            }
            __syncthreads();

            // gate fuse + cell update: 64 threads = 8 batches x 8 j's
            if (tid < 64) {
                int b = tid >> 3, j2 = tid & 7;
                int bb = g2 * 8 + b;
                float s0 = 0.f, s1 = 0.f, s2 = 0.f, s3 = 0.f;
#pragma unroll
                for (int k2 = 0; k2 < 8; k2++) {
                    const float* pp = spart + b * 256 + k2 * 32 + j2;
                    s0 += pp[0];
                    s1 += pp[8];
                    s2 += pp[16];
                    s3 += pp[24];
                }
                const float* xp = g_scratch + XP_OFF + (size_t)dir * 4194304
                                  + (size_t)(bb * NL + t) * 2048;
                int j = j0 + j2;
                float iv = s0 + xp[j];
                float fv = s1 + xp[512 + j];
                float gv = s2 + xp[1024 + j];
                float ov = s3 + xp[1536 + j];
                float cold = sc[bb * 8 + j2];
                float cnew = sigm(fv) * cold + sigm(iv) * tanhf(gv);
                float hnew = sigm(ov) * tanhf(cnew);
                sc[bb * 8 + j2] = cnew;
                g_scratch[HS_OFF + (size_t)dir * 1048576 + (size_t)t * 8192
                          + (size_t)bb * 512 + j] = hnew;
            }
            __syncthreads();
        }

        // ---- grid barrier (monotonic counters, reset by zero_kernel) ----
        if (tid == 0) {
            __threadfence();
            unsigned a = atomicAdd(&g_arrive, 1u) + 1u;
            unsigned target = (unsigned)(128 * (t + 1));
            if (a == target) {
                atomicExch(&g_release, (unsigned)(t + 1));
            } else {
                while (atomicAdd(&g_release, 0u) < (unsigned)(t + 1)) { }
            }
            __threadfence();
        }
        __syncthreads();
    }
}

// ---------------- o = 0.5*(hf + hb_rev) ----------------
__global__ void o_kernel() {
    int idx = blockIdx.x * blockDim.x + threadIdx.x;   // < 1048576
    int row = idx >> 9, j = idx & 511;
    int b = row >> 7, l = row & 127;
    float hf = g_scratch[HS_OFF + (size_t)l * 8192 + (size_t)b * 512 + j];
    float hb = g_scratch[HS_OFF + 1048576 + (size_t)(NL - 1 - l) * 8192 + (size_t)b * 512 + j];
    g_scratch[OBUF_OFF + idx] = 0.5f * (hf + hb);
}

// ---------------- emission: emi = o @ Ew^T + eb ----------------
__global__ void emi_kernel(const float* __restrict__ ew, const float* __restrict__ eb) {
    int idx = blockIdx.x * blockDim.x + threadIdx.x;
    if (idx >= 2048 * NT) return;
    int row = idx / NT, tag = idx - row * NT;
    const float4* o4 = reinterpret_cast<const float4*>(g_scratch + OBUF_OFF + (size_t)row * 512);
    const float4* w4 = reinterpret_cast<const float4*>(ew + (size_t)tag * 512);
    float s = 0.f;
#pragma unroll 4
    for (int k = 0; k < 128; k++) {
        float4 a = o4[k], b = w4[k];
        s += a.x * b.x + a.y * b.y + a.z * b.z + a.w * b.w;
    }
    g_scratch[EMI_OFF + idx] = s + eb[tag];
}

// ---------------- CRF NLL (tiny; 1 block) ----------------
__global__ void crf_kernel(const int* __restrict__ tokens, const int* __restrict__ tags,
                           const float* __restrict__ trans, const float* __restrict__ startv,
                           const float* __restrict__ endv)
{
    __shared__ float st[81], ss[9], se[9];
    __shared__ float alpha[16][9], nxt[16][9];
    __shared__ float num[16];
    __shared__ int prev[16];
    __shared__ float res[16];
    int tid = threadIdx.x;
    if (tid < 81) st[tid] = trans[tid];
    if (tid < 9) { ss[tid] = startv[tid]; se[tid] = endv[tid]; }
    __syncthreads();
    int b = tid / 9, j = tid - b * 9;
    const float* emi = g_scratch + EMI_OFF;
    if (tid < 144) {
        alpha[b][j] = ss[j] + emi[(size_t)(b * NL) * NT + j];
        if (j == 0) {
            int t0 = tags[b * NL];
            num[b] = ss[t0] + emi[(size_t)(b * NL) * NT + t0];
            prev[b] = t0;
        }
    }
    __syncthreads();
    for (int t = 1; t < NL; t++) {
        int m = 0;
        if (tid < 144) {
            m = (tokens[b * NL + t] != 0);
            float mx = -1e30f;
#pragma unroll
            for (int i = 0; i < 9; i++) mx = fmaxf(mx, alpha[b][i] + st[i * 9 + j]);
            float s = 0.f;
#pragma unroll
            for (int i = 0; i < 9; i++) s += expf(alpha[b][i] + st[i * 9 + j] - mx);
            float nv = mx + logf(s) + emi[(size_t)(b * NL + t) * NT + j];
            nxt[b][j] = m ? nv : alpha[b][j];
        }
        __syncthreads();
        if (tid < 144) {
            alpha[b][j] = nxt[b][j];
            if (j == 0 && m) {
                int tg = tags[b * NL + t];
                num[b] += st[prev[b] * 9 + tg] + emi[(size_t)(b * NL + t) * NT + tg];
                prev[b] = tg;
            }
        }
        __syncthreads();
    }
    if (tid < 16) {
        float nb = num[tid] + se[prev[tid]];
        float mx = -1e30f;
        for (int i2 = 0; i2 < 9; i2++) mx = fmaxf(mx, alpha[tid][i2] + se[i2]);
        float s = 0.f;
        for (int i2 = 0; i2 < 9; i2++) s += expf(alpha[tid][i2] + se[i2] - mx);
        res[tid] = nb - (mx + logf(s));
    }
    __syncthreads();
    if (tid == 0) {
        float tot = 0.f;
        for (int i2 = 0; i2 < 16; i2++) tot += res[i2];
        g_crf_loss = -tot / 16.f;
    }
}

// ---------------- oc = concat(o, bio_emb[bio_gold]) ----------------
__global__ void oc_kernel(const int* __restrict__ biog, const float* __restrict__ bemb) {
    int idx = blockIdx.x * blockDim.x + threadIdx.x;   // < 2048*576
    int row = idx / 576, k = idx - row * 576;
    float v = (k < 512) ? g_scratch[OBUF_OFF + (size_t)row * 512 + k]
                        : bemb[(size_t)biog[row] * NBIOE + (k - 512)];
    g_scratch[OC_OFF + idx] = v;
}

// ---------------- fused selection: uv build + einsum + BCE + masked sum -------
// grid 1024 blocks: (b, i-pair where i indexes V). 128 threads = j (indexes U).
__global__ __launch_bounds__(128) void sel_kernel(const int* __restrict__ gold,
                                                  const float* __restrict__ rel,
                                                  const float* __restrict__ uvb)
{
    __shared__ __align__(16) float srel[NR * NREL];   // 25.6KB
    __shared__ __align__(16) float sv0[NREL], sv1[NREL];
    __shared__ float sred[4];

    int bx = blockIdx.x;
    int b  = bx >> 6;
    int i0 = (bx & 63) << 1;
    int tid = threadIdx.x;

    for (int p = tid; p < NR * NREL; p += 128) srel[p] = rel[p];
    const float* v2 = g_scratch + V2_OFF;
    sv0[tid] = v2[(size_t)(b * NL + i0) * NREL + tid] + uvb[tid];
    sv1[tid] = v2[(size_t)(b * NL + i0 + 1) * NREL + tid] + uvb[tid];
    __syncthreads();

    int j = tid;
    const float4* u1r = reinterpret_cast<const float4*>(g_scratch + U1_OFF + (size_t)(b * NL + j) * NREL);
    const float4* s0_4 = reinterpret_cast<const float4*>(sv0);
    const float4* s1_4 = reinterpret_cast<const float4*>(sv1);
    const float4* rel4 = reinterpret_cast<const float4*>(srel);

    float acc0[NR], acc1[NR];
#pragma unroll
    for (int r = 0; r < NR; r++) { acc0[r] = 0.f; acc1[r] = 0.f; }

#pragma unroll 4
    for (int h4 = 0; h4 < 32; h4++) {
        float4 uu = u1r[h4];
        float4 a = s0_4[h4];
        float4 c = s1_4[h4];
        float x0x = fmaxf(uu.x + a.x, 0.f), x0y = fmaxf(uu.y + a.y, 0.f);
        float x0z = fmaxf(uu.z + a.z, 0.f), x0w = fmaxf(uu.w + a.w, 0.f);
        float x1x = fmaxf(uu.x + c.x, 0.f), x1y = fmaxf(uu.y + c.y, 0.f);
        float x1z = fmaxf(uu.z + c.z, 0.f), x1w = fmaxf(uu.w + c.w, 0.f);
#pragma unroll
        for (int r = 0; r < NR; r++) {
            float4 rv = rel4[r * 32 + h4];
            acc0[r] += x0x * rv.x + x0y * rv.y + x0z * rv.z + x0w * rv.w;
            acc1[r] += x1x * rv.x + x1y * rv.y + x1z * rv.z + x1w * rv.w;
        }
    }

    float mi0 = g_scratch[MASKF_OFF + b * NL + i0];
    float mi1 = g_scratch[MASKF_OFF + b * NL + i0 + 1];
    float mj  = g_scratch[MASKF_OFF + b * NL + j];
    const int* g0 = gold + (size_t)(b * NL + i0) * NR * NL + j;
    const int* g1 = gold + (size_t)(b * NL + i0 + 1) * NR * NL + j;
    float s0 = 0.f, s1 = 0.f;
#pragma unroll
    for (int r = 0; r < NR; r++) {
        float x = acc0[r];
        float gg = (float)g0[(size_t)r * NL];
        s0 += fmaxf(x, 0.f) - x * gg + log1pf(expf(-fabsf(x)));
        x = acc1[r];
        gg = (float)g1[(size_t)r * NL];
        s1 += fmaxf(x, 0.f) - x * gg + log1pf(expf(-fabsf(x)));
    }
    float part = mj * (mi0 * s0 + mi1 * s1);

#pragma unroll
    for (int off = 16; off; off >>= 1) part += __shfl_down_sync(0xFFFFFFFFu, part, off);
    if ((tid & 31) == 0) sred[tid >> 5] = part;
    __syncthreads();
    if (tid == 0) {
        double tot = (double)sred[0] + (double)sred[1] + (double)sred[2] + (double)sred[3];
        atomicAdd(&g_sel_sum, tot);
    }
}

// ---------------- final scalar ----------------
__global__ void final_kernel(float* out) {
    out[0] = g_crf_loss + (float)(g_sel_sum / (double)g_mask_count);
}

// ============================================================================
extern "C" void kernel_launch(void* const* d_in, const int* in_sizes, int n_in,
                              void* d_out, int out_size)
{
    const int*   tokens     = (const int*)d_in[0];
    const int*   bio_gold   = (const int*)d_in[1];
    const int*   sel_gold   = (const int*)d_in[2];
    // d_in[3] = is_train (unused)
    const float* word_emb   = (const float*)d_in[4];
    const float* rel_emb    = (const float*)d_in[5];
    const float* bio_emb    = (const float*)d_in[6];
    const float* w_ih_f     = (const float*)d_in[7];
    const float* w_hh_f     = (const float*)d_in[8];
    const float* b_ih_f     = (const float*)d_in[9];
    const float* b_hh_f     = (const float*)d_in[10];
    const float* w_ih_b     = (const float*)d_in[11];
    const float* w_hh_b     = (const float*)d_in[12];
    const float* b_ih_b     = (const float*)d_in[13];
    const float* b_hh_b     = (const float*)d_in[14];
    const float* emission_w = (const float*)d_in[15];
    const float* emission_b = (const float*)d_in[16];
    const float* sel_u_w    = (const float*)d_in[17];
    const float* sel_u_b    = (const float*)d_in[18];
    const float* sel_v_w    = (const float*)d_in[19];
    const float* sel_v_b    = (const float*)d_in[20];
    const float* sel_uv_w   = (const float*)d_in[21];
    const float* sel_uv_b   = (const float*)d_in[22];
    const float* crf_trans  = (const float*)d_in[23];
    const float* crf_start  = (const float*)d_in[24];
    const float* crf_end    = (const float*)d_in[25];

    zero_kernel<<<1, 1>>>();
    embed_kernel<<<2400, 256>>>(tokens, word_emb);
    embrev_kernel<<<2400, 256>>>();
    bsum_kernel<<<16, 256>>>(b_ih_f, b_hh_f, b_ih_b, b_hh_b);

    // xproj: (emb/emb_rev) @ w_ih^T + (b_ih + b_hh)
    sgemm_nt<<<dim3(32, 32), 256>>>(EMB_OFF, NE, w_ih_f, NE,
                                    XP_OFF, 2048, NE, nullptr, BSUM_OFF, 0);
    sgemm_nt<<<dim3(32, 32), 256>>>(EMBR_OFF, NE, w_ih_b, NE,
                                    XP_OFF + 4194304, 2048, NE, nullptr, BSUM_OFF + 2048, 0);

    // persistent BiLSTM over all timesteps (40KB dynamic smem, fits default)
    lstm_persist<<<128, 256, 40960>>>(w_hh_f, w_hh_b);

    o_kernel<<<4096, 256>>>();
    emi_kernel<<<(2048 * NT + 127) / 128, 128>>>(emission_w, emission_b);
    crf_kernel<<<1, 160>>>(tokens, bio_gold, crf_trans, crf_start, crf_end);

    oc_kernel<<<4608, 256>>>(bio_gold, bio_emb);
    // u = relu(oc @ sel_u_w^T + b), v likewise
    sgemm_nt<<<dim3(2, 32), 256>>>(OC_OFF, 576, sel_u_w, 576,
                                   U_OFF, NREL, 576, sel_u_b, -1, 1);
    sgemm_nt<<<dim3(2, 32), 256>>>(OC_OFF, 576, sel_v_w, 576,
                                   V_OFF, NREL, 576, sel_v_b, -1, 1);
    // u1 = u @ w1^T, v2 = v @ w2^T  (w1/w2 = halves of sel_uv_w, ldb=256)
    sgemm_nt<<<dim3(2, 32), 256>>>(U_OFF, NREL, sel_uv_w, 2 * NREL,
                                   U1_OFF, NREL, NREL, nullptr, -1, 0);
    sgemm_nt<<<dim3(2, 32), 256>>>(V_OFF, NREL, sel_uv_w + NREL, 2 * NREL,
                                   V2_OFF, NREL, NREL, nullptr, -1, 0);

    sel_kernel<<<1024, 128>>>(sel_gold, rel_emb, sel_uv_b);
    final_kernel<<<1, 1>>>((float*)d_out);
}